// round 3
// baseline (speedup 1.0000x reference)
#include <cuda_runtime.h>
#include <cuda_bf16.h>

// ---------------------------------------------------------------------------
// SlotGCN: 2-layer GCN, atomic-free aggregation via per-call CSR build.
// Edge index dtype (int32 vs int64) auto-detected on device.
// N=50000, E=600000, C1=128, C2=64, fp32.
// ---------------------------------------------------------------------------

#define MAXN 50000
#define MAXE 600000
#define SCAN_B 512
#define NBLK ((MAXN + SCAN_B - 1) / SCAN_B)   // 98

__device__ float g_h1[MAXN * 128];
__device__ float g_a1[MAXN * 128];
__device__ float g_h2[MAXN * 64];
__device__ float g_dinv[MAXN];
__device__ int   g_cnt[MAXN];        // in-degree
__device__ int   g_rowptr[MAXN + 1];
__device__ int   g_pos[MAXN];        // build cursors
__device__ int   g_csr[MAXE];        // src per edge, grouped by dst
__device__ int   g_bsum[NBLK];
__device__ int   g_boff[NBLK];
__device__ int   g_is64;             // 1 if edge_index is int64, 0 if int32

// Fetch edge index at flat position pos (0..2E-1), dtype per flag.
__device__ __forceinline__ int load_idx(const void* ei, long long pos, int is64) {
    if (is64) return (int)((const long long*)ei)[pos];
    return ((const int*)ei)[pos];
}

// ---------------- dtype detection -------------------------------------------
// If data is int64 (values in [0, 50000)), every odd 32-bit word is 0.
__global__ void detect_kernel(const int* __restrict__ ei32, long long half_words) {
    __shared__ int nz;
    if (threadIdx.x == 0) nz = 0;
    __syncthreads();
    for (int k = threadIdx.x; k < 4096; k += blockDim.x) {
        long long w = ((long long)k * 1315423911u) % half_words;
        if (ei32[2 * w + 1] != 0) atomicAdd(&nz, 1);
    }
    __syncthreads();
    if (threadIdx.x == 0) g_is64 = (nz == 0) ? 1 : 0;
}

// ---------------- zero degree counters --------------------------------------
__global__ void zero_kernel(int N) {
    int i = blockIdx.x * blockDim.x + threadIdx.x;
    if (i < N) g_cnt[i] = 0;
}

// ---------------- in-degree count -------------------------------------------
__global__ void deg_kernel(const void* __restrict__ ei, int E, int N) {
    int e = blockIdx.x * blockDim.x + threadIdx.x;
    if (e >= E) return;
    int is64 = g_is64;
    int d = load_idx(ei, (long long)E + e, is64);
    if ((unsigned)d < (unsigned)N) atomicAdd(&g_cnt[d], 1);
}

__global__ void dinv_kernel(int N) {
    int i = blockIdx.x * blockDim.x + threadIdx.x;
    if (i < N) g_dinv[i] = rsqrtf((float)g_cnt[i] + 1.0f);
}

// ---------------- exclusive scan of g_cnt -> g_rowptr ------------------------
__global__ void scan1_kernel(int N) {
    __shared__ int sh[SCAN_B];
    int t = threadIdx.x;
    int i = blockIdx.x * SCAN_B + t;
    int v = (i < N) ? g_cnt[i] : 0;
    sh[t] = v;
    __syncthreads();
#pragma unroll
    for (int o = 1; o < SCAN_B; o <<= 1) {
        int x = (t >= o) ? sh[t - o] : 0;
        __syncthreads();
        sh[t] += x;
        __syncthreads();
    }
    if (i < N) g_rowptr[i] = sh[t] - v;          // exclusive within block
    if (t == SCAN_B - 1) g_bsum[blockIdx.x] = sh[t];
}

__global__ void scan2_kernel(int nb) {
    if (threadIdx.x == 0) {
        int acc = 0;
        for (int b = 0; b < nb; b++) { g_boff[b] = acc; acc += g_bsum[b]; }
    }
}

__global__ void scan3_kernel(int N, int E) {
    int i = blockIdx.x * blockDim.x + threadIdx.x;
    if (i < N) {
        int r = g_rowptr[i] + g_boff[i / SCAN_B];
        g_rowptr[i] = r;
        g_pos[i] = r;
    }
    if (i == 0) g_rowptr[N] = E;
}

// ---------------- CSR build ---------------------------------------------------
__global__ void build_kernel(const void* __restrict__ ei, int E, int N) {
    int e = blockIdx.x * blockDim.x + threadIdx.x;
    if (e >= E) return;
    int is64 = g_is64;
    int d = load_idx(ei, (long long)E + e, is64);
    int s = load_idx(ei, (long long)e, is64);
    if ((unsigned)d < (unsigned)N && (unsigned)s < (unsigned)N) {
        int p = atomicAdd(&g_pos[d], 1);
        if (p < MAXE) g_csr[p] = s;
    }
}

// ---------------- GEMM: H[N,C] = X[N,128] @ W[128,C] ------------------------
template <int C>
__device__ __forceinline__ void gemm_body(const float* __restrict__ X,
                                          const float* __restrict__ W,
                                          float* __restrict__ H, int N) {
    constexpr int CT = C / 4;
    __shared__ float xs[32][33];
    __shared__ float ws[32][C];
    const int tid  = threadIdx.x;
    const int ct   = tid % CT;
    const int rt   = tid / CT;
    const int row0 = blockIdx.x * 32;
    const int nthr = CT * 8;

    float acc[4][4];
#pragma unroll
    for (int r = 0; r < 4; r++)
#pragma unroll
        for (int c = 0; c < 4; c++) acc[r][c] = 0.f;

    for (int k0 = 0; k0 < 128; k0 += 32) {
        for (int i = tid; i < 32 * 32; i += nthr) {
            int r = i >> 5, k = i & 31;
            int grow = row0 + r;
            xs[r][k] = (grow < N) ? X[(long long)grow * 128 + k0 + k] : 0.f;
        }
        for (int i = tid; i < 32 * C; i += nthr) {
            int k = i / C, c = i % C;
            ws[k][c] = W[(k0 + k) * C + c];
        }
        __syncthreads();
#pragma unroll
        for (int k = 0; k < 32; k++) {
            float4 b = *reinterpret_cast<const float4*>(&ws[k][ct * 4]);
#pragma unroll
            for (int r = 0; r < 4; r++) {
                float a = xs[rt * 4 + r][k];
                acc[r][0] = fmaf(a, b.x, acc[r][0]);
                acc[r][1] = fmaf(a, b.y, acc[r][1]);
                acc[r][2] = fmaf(a, b.z, acc[r][2]);
                acc[r][3] = fmaf(a, b.w, acc[r][3]);
            }
        }
        __syncthreads();
    }
#pragma unroll
    for (int r = 0; r < 4; r++) {
        int grow = row0 + rt * 4 + r;
        if (grow < N) {
            float4 v = make_float4(acc[r][0], acc[r][1], acc[r][2], acc[r][3]);
            *reinterpret_cast<float4*>(&H[(long long)grow * C + ct * 4]) = v;
        }
    }
}

__global__ void gemm1_kernel(const float* __restrict__ X,
                             const float* __restrict__ W, int N) {
    gemm_body<128>(X, W, g_h1, N);
}
__global__ void gemm2_kernel(const float* __restrict__ W, int N) {
    gemm_body<64>(g_a1, W, g_h2, N);
}

// ---------------- fused gather + epilogue, warp per node --------------------
// Layer 1: C=128, lane owns float4 at col lane*4.
__global__ void gather1_kernel(const float* __restrict__ b1, int N) {
    int w    = (blockIdx.x * blockDim.x + threadIdx.x) >> 5;
    int lane = threadIdx.x & 31;
    if (w >= N) return;
    float dd = g_dinv[w];
    const float4* h1v = reinterpret_cast<const float4*>(g_h1);
    float4 v = h1v[(long long)w * 32 + lane];
    float4 acc = make_float4(v.x * dd, v.y * dd, v.z * dd, v.w * dd);  // self loop
    int j  = g_rowptr[w];
    int j1 = g_rowptr[w + 1];
    for (; j + 1 < j1; j += 2) {
        int s0 = g_csr[j], s1 = g_csr[j + 1];
        float w0 = g_dinv[s0], w1 = g_dinv[s1];
        float4 u0 = h1v[(long long)s0 * 32 + lane];
        float4 u1 = h1v[(long long)s1 * 32 + lane];
        acc.x = fmaf(u0.x, w0, acc.x); acc.y = fmaf(u0.y, w0, acc.y);
        acc.z = fmaf(u0.z, w0, acc.z); acc.w = fmaf(u0.w, w0, acc.w);
        acc.x = fmaf(u1.x, w1, acc.x); acc.y = fmaf(u1.y, w1, acc.y);
        acc.z = fmaf(u1.z, w1, acc.z); acc.w = fmaf(u1.w, w1, acc.w);
    }
    if (j < j1) {
        int s0 = g_csr[j];
        float w0 = g_dinv[s0];
        float4 u0 = h1v[(long long)s0 * 32 + lane];
        acc.x = fmaf(u0.x, w0, acc.x); acc.y = fmaf(u0.y, w0, acc.y);
        acc.z = fmaf(u0.z, w0, acc.z); acc.w = fmaf(u0.w, w0, acc.w);
    }
    float4 bb = reinterpret_cast<const float4*>(b1)[lane];
    float4 o;
    o.x = fmaxf(fmaf(acc.x, dd, bb.x), 0.f);
    o.y = fmaxf(fmaf(acc.y, dd, bb.y), 0.f);
    o.z = fmaxf(fmaf(acc.z, dd, bb.z), 0.f);
    o.w = fmaxf(fmaf(acc.w, dd, bb.w), 0.f);
    reinterpret_cast<float4*>(g_a1)[(long long)w * 32 + lane] = o;
}

// Layer 2: C=64, lane owns float2 at col lane*2.
__global__ void gather2_kernel(const float* __restrict__ b2,
                               float* __restrict__ out, int N) {
    int w    = (blockIdx.x * blockDim.x + threadIdx.x) >> 5;
    int lane = threadIdx.x & 31;
    if (w >= N) return;
    float dd = g_dinv[w];
    const float2* h2v = reinterpret_cast<const float2*>(g_h2);
    float2 v = h2v[(long long)w * 32 + lane];
    float2 acc = make_float2(v.x * dd, v.y * dd);
    int j  = g_rowptr[w];
    int j1 = g_rowptr[w + 1];
    for (; j + 1 < j1; j += 2) {
        int s0 = g_csr[j], s1 = g_csr[j + 1];
        float w0 = g_dinv[s0], w1 = g_dinv[s1];
        float2 u0 = h2v[(long long)s0 * 32 + lane];
        float2 u1 = h2v[(long long)s1 * 32 + lane];
        acc.x = fmaf(u0.x, w0, acc.x); acc.y = fmaf(u0.y, w0, acc.y);
        acc.x = fmaf(u1.x, w1, acc.x); acc.y = fmaf(u1.y, w1, acc.y);
    }
    if (j < j1) {
        int s0 = g_csr[j];
        float w0 = g_dinv[s0];
        float2 u0 = h2v[(long long)s0 * 32 + lane];
        acc.x = fmaf(u0.x, w0, acc.x); acc.y = fmaf(u0.y, w0, acc.y);
    }
    float2 bb = reinterpret_cast<const float2*>(b2)[lane];
    float2 o;
    o.x = fmaf(acc.x, dd, bb.x);
    o.y = fmaf(acc.y, dd, bb.y);
    reinterpret_cast<float2*>(out)[(long long)w * 32 + lane] = o;
}

// ---------------- launch ------------------------------------------------------
extern "C" void kernel_launch(void* const* d_in, const int* in_sizes, int n_in,
                              void* d_out, int out_size) {
    const float* x   = (const float*)d_in[0];
    const void*  ei  = d_in[1];
    const float* W1  = (const float*)d_in[2];
    const float* b1  = (const float*)d_in[3];
    const float* W2  = (const float*)d_in[4];
    const float* b2  = (const float*)d_in[5];
    float*       out = (float*)d_out;

    const int N = in_sizes[0] / 128;      // 50000
    const int E = in_sizes[1] / 2;        // 600000 (element count / 2 either dtype)

    const int TB = 256;
    const int nb = (N + SCAN_B - 1) / SCAN_B;

    // dtype detect + CSR build chain
    detect_kernel<<<1, 256>>>((const int*)ei, (long long)E);
    zero_kernel<<<(N + TB - 1) / TB, TB>>>(N);
    deg_kernel<<<(E + TB - 1) / TB, TB>>>(ei, E, N);
    dinv_kernel<<<(N + TB - 1) / TB, TB>>>(N);
    scan1_kernel<<<nb, SCAN_B>>>(N);
    scan2_kernel<<<1, 32>>>(nb);
    scan3_kernel<<<(N + TB - 1) / TB, TB>>>(N, E);
    build_kernel<<<(E + TB - 1) / TB, TB>>>(ei, E, N);

    // layer 1
    gemm1_kernel<<<(N + 31) / 32, 256>>>(x, W1, N);
    gather1_kernel<<<(N * 32 + TB - 1) / TB, TB>>>(b1, N);

    // layer 2
    gemm2_kernel<<<(N + 31) / 32, 128>>>(W2, N);
    gather2_kernel<<<(N * 32 + TB - 1) / TB, TB>>>(b2, out, N);
}

// round 4
// speedup vs baseline: 1.0309x; 1.0309x over previous
#include <cuda_runtime.h>
#include <cuda_bf16.h>

// ---------------------------------------------------------------------------
// SlotGCN: 2-layer GCN, atomic-free aggregation via per-call CSR build.
// Edge index dtype (int32 vs int64) auto-detected on device.
// N=50000, E=600000, C1=128, C2=64, fp32.
// ---------------------------------------------------------------------------

#define MAXN 50000
#define MAXE 600000
#define SCAN_B 512
#define NBLK ((MAXN + SCAN_B - 1) / SCAN_B)   // 98

__device__ float g_h1[MAXN * 128];
__device__ float g_a1[MAXN * 128];
__device__ float g_h2[MAXN * 64];
__device__ float g_dinv[MAXN];
__device__ int   g_cnt[MAXN];        // in-degree
__device__ int   g_rowptr[MAXN + 1];
__device__ int   g_pos[MAXN];        // build cursors
__device__ int   g_csr[MAXE];        // src per edge, grouped by dst
__device__ int   g_bsum[NBLK];
__device__ int   g_boff[NBLK];
__device__ int   g_is64;             // 1 if edge_index is int64, 0 if int32

// Fetch edge index at flat position pos (0..2E-1), dtype per flag.
__device__ __forceinline__ int load_idx(const void* ei, long long pos, int is64) {
    if (is64) return (int)((const long long*)ei)[pos];
    return ((const int*)ei)[pos];
}

// ---------------- dtype detection -------------------------------------------
// If data is int64 (values in [0, 50000)), every odd 32-bit word is 0.
__global__ void detect_kernel(const int* __restrict__ ei32, long long half_words) {
    __shared__ int nz;
    if (threadIdx.x == 0) nz = 0;
    __syncthreads();
    for (int k = threadIdx.x; k < 4096; k += blockDim.x) {
        long long w = ((long long)k * 1315423911u) % half_words;
        if (ei32[2 * w + 1] != 0) atomicAdd(&nz, 1);
    }
    __syncthreads();
    if (threadIdx.x == 0) g_is64 = (nz == 0) ? 1 : 0;
}

// ---------------- zero degree counters --------------------------------------
__global__ void zero_kernel(int N) {
    int i = blockIdx.x * blockDim.x + threadIdx.x;
    if (i < N) g_cnt[i] = 0;
}

// ---------------- in-degree count -------------------------------------------
__global__ void deg_kernel(const void* __restrict__ ei, int E, int N) {
    int e = blockIdx.x * blockDim.x + threadIdx.x;
    if (e >= E) return;
    int is64 = g_is64;
    int d = load_idx(ei, (long long)E + e, is64);
    if ((unsigned)d < (unsigned)N) atomicAdd(&g_cnt[d], 1);
}

__global__ void dinv_kernel(int N) {
    int i = blockIdx.x * blockDim.x + threadIdx.x;
    if (i < N) g_dinv[i] = rsqrtf((float)g_cnt[i] + 1.0f);
}

// ---------------- exclusive scan of g_cnt -> g_rowptr ------------------------
__global__ void scan1_kernel(int N) {
    __shared__ int sh[SCAN_B];
    int t = threadIdx.x;
    int i = blockIdx.x * SCAN_B + t;
    int v = (i < N) ? g_cnt[i] : 0;
    sh[t] = v;
    __syncthreads();
#pragma unroll
    for (int o = 1; o < SCAN_B; o <<= 1) {
        int x = (t >= o) ? sh[t - o] : 0;
        __syncthreads();
        sh[t] += x;
        __syncthreads();
    }
    if (i < N) g_rowptr[i] = sh[t] - v;          // exclusive within block
    if (t == SCAN_B - 1) g_bsum[blockIdx.x] = sh[t];
}

__global__ void scan2_kernel(int nb) {
    if (threadIdx.x == 0) {
        int acc = 0;
        for (int b = 0; b < nb; b++) { g_boff[b] = acc; acc += g_bsum[b]; }
    }
}

__global__ void scan3_kernel(int N, int E) {
    int i = blockIdx.x * blockDim.x + threadIdx.x;
    if (i < N) {
        int r = g_rowptr[i] + g_boff[i / SCAN_B];
        g_rowptr[i] = r;
        g_pos[i] = r;
    }
    if (i == 0) g_rowptr[N] = E;
}

// ---------------- CSR build ---------------------------------------------------
__global__ void build_kernel(const void* __restrict__ ei, int E, int N) {
    int e = blockIdx.x * blockDim.x + threadIdx.x;
    if (e >= E) return;
    int is64 = g_is64;
    int d = load_idx(ei, (long long)E + e, is64);
    int s = load_idx(ei, (long long)e, is64);
    if ((unsigned)d < (unsigned)N && (unsigned)s < (unsigned)N) {
        int p = atomicAdd(&g_pos[d], 1);
        if (p < MAXE) g_csr[p] = s;
    }
}

// ---------------- GEMM: H[N,C] = X[N,128] @ W[128,C] ------------------------
template <int C>
__device__ __forceinline__ void gemm_body(const float* __restrict__ X,
                                          const float* __restrict__ W,
                                          float* __restrict__ H, int N) {
    constexpr int CT = C / 4;
    __shared__ float xs[32][33];
    __shared__ float ws[32][C];
    const int tid  = threadIdx.x;
    const int ct   = tid % CT;
    const int rt   = tid / CT;
    const int row0 = blockIdx.x * 32;
    const int nthr = CT * 8;

    float acc[4][4];
#pragma unroll
    for (int r = 0; r < 4; r++)
#pragma unroll
        for (int c = 0; c < 4; c++) acc[r][c] = 0.f;

    for (int k0 = 0; k0 < 128; k0 += 32) {
        for (int i = tid; i < 32 * 32; i += nthr) {
            int r = i >> 5, k = i & 31;
            int grow = row0 + r;
            xs[r][k] = (grow < N) ? X[(long long)grow * 128 + k0 + k] : 0.f;
        }
        for (int i = tid; i < 32 * C; i += nthr) {
            int k = i / C, c = i % C;
            ws[k][c] = W[(k0 + k) * C + c];
        }
        __syncthreads();
#pragma unroll
        for (int k = 0; k < 32; k++) {
            float4 b = *reinterpret_cast<const float4*>(&ws[k][ct * 4]);
#pragma unroll
            for (int r = 0; r < 4; r++) {
                float a = xs[rt * 4 + r][k];
                acc[r][0] = fmaf(a, b.x, acc[r][0]);
                acc[r][1] = fmaf(a, b.y, acc[r][1]);
                acc[r][2] = fmaf(a, b.z, acc[r][2]);
                acc[r][3] = fmaf(a, b.w, acc[r][3]);
            }
        }
        __syncthreads();
    }
#pragma unroll
    for (int r = 0; r < 4; r++) {
        int grow = row0 + rt * 4 + r;
        if (grow < N) {
            float4 v = make_float4(acc[r][0], acc[r][1], acc[r][2], acc[r][3]);
            *reinterpret_cast<float4*>(&H[(long long)grow * C + ct * 4]) = v;
        }
    }
}

__global__ void gemm1_kernel(const float* __restrict__ X,
                             const float* __restrict__ W, int N) {
    gemm_body<128>(X, W, g_h1, N);
}
__global__ void gemm2_kernel(const float* __restrict__ W, int N) {
    gemm_body<64>(g_a1, W, g_h2, N);
}

// ---------------- fused gather + epilogue, warp per node --------------------
// Layer 1: C=128, lane owns float4 at col lane*4.
__global__ void gather1_kernel(const float* __restrict__ b1, int N) {
    int w    = (blockIdx.x * blockDim.x + threadIdx.x) >> 5;
    int lane = threadIdx.x & 31;
    if (w >= N) return;
    float dd = g_dinv[w];
    const float4* h1v = reinterpret_cast<const float4*>(g_h1);
    float4 v = h1v[(long long)w * 32 + lane];
    float4 acc = make_float4(v.x * dd, v.y * dd, v.z * dd, v.w * dd);  // self loop
    int j  = g_rowptr[w];
    int j1 = g_rowptr[w + 1];
    for (; j + 1 < j1; j += 2) {
        int s0 = g_csr[j], s1 = g_csr[j + 1];
        float w0 = g_dinv[s0], w1 = g_dinv[s1];
        float4 u0 = h1v[(long long)s0 * 32 + lane];
        float4 u1 = h1v[(long long)s1 * 32 + lane];
        acc.x = fmaf(u0.x, w0, acc.x); acc.y = fmaf(u0.y, w0, acc.y);
        acc.z = fmaf(u0.z, w0, acc.z); acc.w = fmaf(u0.w, w0, acc.w);
        acc.x = fmaf(u1.x, w1, acc.x); acc.y = fmaf(u1.y, w1, acc.y);
        acc.z = fmaf(u1.z, w1, acc.z); acc.w = fmaf(u1.w, w1, acc.w);
    }
    if (j < j1) {
        int s0 = g_csr[j];
        float w0 = g_dinv[s0];
        float4 u0 = h1v[(long long)s0 * 32 + lane];
        acc.x = fmaf(u0.x, w0, acc.x); acc.y = fmaf(u0.y, w0, acc.y);
        acc.z = fmaf(u0.z, w0, acc.z); acc.w = fmaf(u0.w, w0, acc.w);
    }
    float4 bb = reinterpret_cast<const float4*>(b1)[lane];
    float4 o;
    o.x = fmaxf(fmaf(acc.x, dd, bb.x), 0.f);
    o.y = fmaxf(fmaf(acc.y, dd, bb.y), 0.f);
    o.z = fmaxf(fmaf(acc.z, dd, bb.z), 0.f);
    o.w = fmaxf(fmaf(acc.w, dd, bb.w), 0.f);
    reinterpret_cast<float4*>(g_a1)[(long long)w * 32 + lane] = o;
}

// Layer 2: C=64, lane owns float2 at col lane*2.
__global__ void gather2_kernel(const float* __restrict__ b2,
                               float* __restrict__ out, int N) {
    int w    = (blockIdx.x * blockDim.x + threadIdx.x) >> 5;
    int lane = threadIdx.x & 31;
    if (w >= N) return;
    float dd = g_dinv[w];
    const float2* h2v = reinterpret_cast<const float2*>(g_h2);
    float2 v = h2v[(long long)w * 32 + lane];
    float2 acc = make_float2(v.x * dd, v.y * dd);
    int j  = g_rowptr[w];
    int j1 = g_rowptr[w + 1];
    for (; j + 1 < j1; j += 2) {
        int s0 = g_csr[j], s1 = g_csr[j + 1];
        float w0 = g_dinv[s0], w1 = g_dinv[s1];
        float2 u0 = h2v[(long long)s0 * 32 + lane];
        float2 u1 = h2v[(long long)s1 * 32 + lane];
        acc.x = fmaf(u0.x, w0, acc.x); acc.y = fmaf(u0.y, w0, acc.y);
        acc.x = fmaf(u1.x, w1, acc.x); acc.y = fmaf(u1.y, w1, acc.y);
    }
    if (j < j1) {
        int s0 = g_csr[j];
        float w0 = g_dinv[s0];
        float2 u0 = h2v[(long long)s0 * 32 + lane];
        acc.x = fmaf(u0.x, w0, acc.x); acc.y = fmaf(u0.y, w0, acc.y);
    }
    float2 bb = reinterpret_cast<const float2*>(b2)[lane];
    float2 o;
    o.x = fmaf(acc.x, dd, bb.x);
    o.y = fmaf(acc.y, dd, bb.y);
    reinterpret_cast<float2*>(out)[(long long)w * 32 + lane] = o;
}

// ---------------- launch ------------------------------------------------------
extern "C" void kernel_launch(void* const* d_in, const int* in_sizes, int n_in,
                              void* d_out, int out_size) {
    const float* x   = (const float*)d_in[0];
    const void*  ei  = d_in[1];
    const float* W1  = (const float*)d_in[2];
    const float* b1  = (const float*)d_in[3];
    const float* W2  = (const float*)d_in[4];
    const float* b2  = (const float*)d_in[5];
    float*       out = (float*)d_out;

    const int N = in_sizes[0] / 128;      // 50000
    const int E = in_sizes[1] / 2;        // 600000 (element count / 2 either dtype)

    const int TB = 256;
    const int nb = (N + SCAN_B - 1) / SCAN_B;

    // dtype detect + CSR build chain
    detect_kernel<<<1, 256>>>((const int*)ei, (long long)E);
    zero_kernel<<<(N + TB - 1) / TB, TB>>>(N);
    deg_kernel<<<(E + TB - 1) / TB, TB>>>(ei, E, N);
    dinv_kernel<<<(N + TB - 1) / TB, TB>>>(N);
    scan1_kernel<<<nb, SCAN_B>>>(N);
    scan2_kernel<<<1, 32>>>(nb);
    scan3_kernel<<<(N + TB - 1) / TB, TB>>>(N, E);
    build_kernel<<<(E + TB - 1) / TB, TB>>>(ei, E, N);

    // layer 1
    gemm1_kernel<<<(N + 31) / 32, 256>>>(x, W1, N);
    gather1_kernel<<<(N * 32 + TB - 1) / TB, TB>>>(b1, N);

    // layer 2
    gemm2_kernel<<<(N + 31) / 32, 128>>>(W2, N);
    gather2_kernel<<<(N * 32 + TB - 1) / TB, TB>>>(b2, out, N);
}

// round 5
// speedup vs baseline: 1.2345x; 1.1976x over previous
#include <cuda_runtime.h>
#include <cuda_bf16.h>

// ---------------------------------------------------------------------------
// SlotGCN: 2-layer GCN, atomic-free aggregation via per-call CSR build.
// R5: side-stream overlap of CSR chain with GEMM1, kernel fusion, gather MLP.
// N=50000, E=600000, C1=128, C2=64, fp32. Edge dtype auto-detected.
// ---------------------------------------------------------------------------

#define MAXN 50000
#define MAXE 600000
#define SCAN_B 512
#define NBLK ((MAXN + SCAN_B - 1) / SCAN_B)   // 98

__device__ float g_h1[MAXN * 128];
__device__ float g_a1[MAXN * 128];
__device__ float g_h2[MAXN * 64];
__device__ float g_dinv[MAXN];
__device__ int   g_cnt[MAXN];
__device__ int   g_rowptr[MAXN + 1];
__device__ int   g_pos[MAXN];
__device__ int   g_csr[MAXE];
__device__ int   g_bsum[NBLK];
__device__ int   g_boff[NBLK];
__device__ int   g_is64;

__device__ __forceinline__ int load_idx(const void* ei, long long pos, int is64) {
    if (is64) return (int)((const long long*)ei)[pos];
    return ((const int*)ei)[pos];
}

// ---------------- fused: zero counters + dtype detection ---------------------
__global__ void detect_zero_kernel(const int* __restrict__ ei32,
                                   long long half_words, int N) {
    int i = blockIdx.x * blockDim.x + threadIdx.x;
    if (i < N) g_cnt[i] = 0;
    if (blockIdx.x == 0) {
        __shared__ int nz;
        if (threadIdx.x == 0) nz = 0;
        __syncthreads();
        for (int k = threadIdx.x; k < 4096; k += blockDim.x) {
            long long w = ((long long)k * 1315423911u) % half_words;
            if (ei32[2 * w + 1] != 0) atomicAdd(&nz, 1);
        }
        __syncthreads();
        if (threadIdx.x == 0) g_is64 = (nz == 0) ? 1 : 0;
    }
}

// ---------------- in-degree count -------------------------------------------
__global__ void deg_kernel(const void* __restrict__ ei, int E, int N) {
    int e = blockIdx.x * blockDim.x + threadIdx.x;
    if (e >= E) return;
    int is64 = g_is64;
    int d = load_idx(ei, (long long)E + e, is64);
    if ((unsigned)d < (unsigned)N) atomicAdd(&g_cnt[d], 1);
}

// ---------------- scan stage 1 (fused dinv) -----------------------------------
__global__ void scan1_kernel(int N) {
    __shared__ int sh[SCAN_B];
    int t = threadIdx.x;
    int i = blockIdx.x * SCAN_B + t;
    int v = (i < N) ? g_cnt[i] : 0;
    if (i < N) g_dinv[i] = rsqrtf((float)v + 1.0f);
    sh[t] = v;
    __syncthreads();
#pragma unroll
    for (int o = 1; o < SCAN_B; o <<= 1) {
        int x = (t >= o) ? sh[t - o] : 0;
        __syncthreads();
        sh[t] += x;
        __syncthreads();
    }
    if (i < N) g_rowptr[i] = sh[t] - v;
    if (t == SCAN_B - 1) g_bsum[blockIdx.x] = sh[t];
}

__global__ void scan2_kernel(int nb) {
    if (threadIdx.x == 0) {
        int acc = 0;
        for (int b = 0; b < nb; b++) { g_boff[b] = acc; acc += g_bsum[b]; }
    }
}

__global__ void scan3_kernel(int N, int E) {
    int i = blockIdx.x * blockDim.x + threadIdx.x;
    if (i < N) {
        int r = g_rowptr[i] + g_boff[i / SCAN_B];
        g_rowptr[i] = r;
        g_pos[i] = r;
    }
    if (i == 0) g_rowptr[N] = E;
}

// ---------------- CSR build ---------------------------------------------------
__global__ void build_kernel(const void* __restrict__ ei, int E, int N) {
    int e = blockIdx.x * blockDim.x + threadIdx.x;
    if (e >= E) return;
    int is64 = g_is64;
    int d = load_idx(ei, (long long)E + e, is64);
    int s = load_idx(ei, (long long)e, is64);
    if ((unsigned)d < (unsigned)N && (unsigned)s < (unsigned)N) {
        int p = atomicAdd(&g_pos[d], 1);
        if (p < MAXE) g_csr[p] = s;
    }
}

// ---------------- GEMM: H[N,C] = X[N,128] @ W[128,C] ------------------------
template <int C>
__device__ __forceinline__ void gemm_body(const float* __restrict__ X,
                                          const float* __restrict__ W,
                                          float* __restrict__ H, int N) {
    constexpr int CT = C / 4;
    __shared__ float xs[32][33];
    __shared__ float ws[32][C];
    const int tid  = threadIdx.x;
    const int ct   = tid % CT;
    const int rt   = tid / CT;
    const int row0 = blockIdx.x * 32;
    const int nthr = CT * 8;

    float acc[4][4];
#pragma unroll
    for (int r = 0; r < 4; r++)
#pragma unroll
        for (int c = 0; c < 4; c++) acc[r][c] = 0.f;

    for (int k0 = 0; k0 < 128; k0 += 32) {
        for (int i = tid; i < 32 * 32; i += nthr) {
            int r = i >> 5, k = i & 31;
            int grow = row0 + r;
            xs[r][k] = (grow < N) ? X[(long long)grow * 128 + k0 + k] : 0.f;
        }
        for (int i = tid; i < 32 * C; i += nthr) {
            int k = i / C, c = i % C;
            ws[k][c] = W[(k0 + k) * C + c];
        }
        __syncthreads();
#pragma unroll
        for (int k = 0; k < 32; k++) {
            float4 b = *reinterpret_cast<const float4*>(&ws[k][ct * 4]);
#pragma unroll
            for (int r = 0; r < 4; r++) {
                float a = xs[rt * 4 + r][k];
                acc[r][0] = fmaf(a, b.x, acc[r][0]);
                acc[r][1] = fmaf(a, b.y, acc[r][1]);
                acc[r][2] = fmaf(a, b.z, acc[r][2]);
                acc[r][3] = fmaf(a, b.w, acc[r][3]);
            }
        }
        __syncthreads();
    }
#pragma unroll
    for (int r = 0; r < 4; r++) {
        int grow = row0 + rt * 4 + r;
        if (grow < N) {
            float4 v = make_float4(acc[r][0], acc[r][1], acc[r][2], acc[r][3]);
            *reinterpret_cast<float4*>(&H[(long long)grow * C + ct * 4]) = v;
        }
    }
}

__global__ void gemm1_kernel(const float* __restrict__ X,
                             const float* __restrict__ W, int N) {
    gemm_body<128>(X, W, g_h1, N);
}
__global__ void gemm2_kernel(const float* __restrict__ W, int N) {
    gemm_body<64>(g_a1, W, g_h2, N);
}

// ---------------- fused gather + epilogue, warp per node --------------------
__global__ void gather1_kernel(const float* __restrict__ b1, int N) {
    int w    = (blockIdx.x * blockDim.x + threadIdx.x) >> 5;
    int lane = threadIdx.x & 31;
    if (w >= N) return;
    float dd = g_dinv[w];
    const float4* h1v = reinterpret_cast<const float4*>(g_h1);
    float4 v = h1v[(long long)w * 32 + lane];
    float4 acc = make_float4(v.x * dd, v.y * dd, v.z * dd, v.w * dd);
    int j  = g_rowptr[w];
    int j1 = g_rowptr[w + 1];
    for (; j + 3 < j1; j += 4) {
        int s0 = g_csr[j], s1 = g_csr[j + 1], s2 = g_csr[j + 2], s3 = g_csr[j + 3];
        float w0 = g_dinv[s0], w1 = g_dinv[s1], w2 = g_dinv[s2], w3 = g_dinv[s3];
        float4 u0 = h1v[(long long)s0 * 32 + lane];
        float4 u1 = h1v[(long long)s1 * 32 + lane];
        float4 u2 = h1v[(long long)s2 * 32 + lane];
        float4 u3 = h1v[(long long)s3 * 32 + lane];
        acc.x = fmaf(u0.x, w0, acc.x); acc.y = fmaf(u0.y, w0, acc.y);
        acc.z = fmaf(u0.z, w0, acc.z); acc.w = fmaf(u0.w, w0, acc.w);
        acc.x = fmaf(u1.x, w1, acc.x); acc.y = fmaf(u1.y, w1, acc.y);
        acc.z = fmaf(u1.z, w1, acc.z); acc.w = fmaf(u1.w, w1, acc.w);
        acc.x = fmaf(u2.x, w2, acc.x); acc.y = fmaf(u2.y, w2, acc.y);
        acc.z = fmaf(u2.z, w2, acc.z); acc.w = fmaf(u2.w, w2, acc.w);
        acc.x = fmaf(u3.x, w3, acc.x); acc.y = fmaf(u3.y, w3, acc.y);
        acc.z = fmaf(u3.z, w3, acc.z); acc.w = fmaf(u3.w, w3, acc.w);
    }
    for (; j < j1; ++j) {
        int s0 = g_csr[j];
        float w0 = g_dinv[s0];
        float4 u0 = h1v[(long long)s0 * 32 + lane];
        acc.x = fmaf(u0.x, w0, acc.x); acc.y = fmaf(u0.y, w0, acc.y);
        acc.z = fmaf(u0.z, w0, acc.z); acc.w = fmaf(u0.w, w0, acc.w);
    }
    float4 bb = reinterpret_cast<const float4*>(b1)[lane];
    float4 o;
    o.x = fmaxf(fmaf(acc.x, dd, bb.x), 0.f);
    o.y = fmaxf(fmaf(acc.y, dd, bb.y), 0.f);
    o.z = fmaxf(fmaf(acc.z, dd, bb.z), 0.f);
    o.w = fmaxf(fmaf(acc.w, dd, bb.w), 0.f);
    reinterpret_cast<float4*>(g_a1)[(long long)w * 32 + lane] = o;
}

__global__ void gather2_kernel(const float* __restrict__ b2,
                               float* __restrict__ out, int N) {
    int w    = (blockIdx.x * blockDim.x + threadIdx.x) >> 5;
    int lane = threadIdx.x & 31;
    if (w >= N) return;
    float dd = g_dinv[w];
    const float2* h2v = reinterpret_cast<const float2*>(g_h2);
    float2 v = h2v[(long long)w * 32 + lane];
    float2 acc = make_float2(v.x * dd, v.y * dd);
    int j  = g_rowptr[w];
    int j1 = g_rowptr[w + 1];
    for (; j + 3 < j1; j += 4) {
        int s0 = g_csr[j], s1 = g_csr[j + 1], s2 = g_csr[j + 2], s3 = g_csr[j + 3];
        float w0 = g_dinv[s0], w1 = g_dinv[s1], w2 = g_dinv[s2], w3 = g_dinv[s3];
        float2 u0 = h2v[(long long)s0 * 32 + lane];
        float2 u1 = h2v[(long long)s1 * 32 + lane];
        float2 u2 = h2v[(long long)s2 * 32 + lane];
        float2 u3 = h2v[(long long)s3 * 32 + lane];
        acc.x = fmaf(u0.x, w0, acc.x); acc.y = fmaf(u0.y, w0, acc.y);
        acc.x = fmaf(u1.x, w1, acc.x); acc.y = fmaf(u1.y, w1, acc.y);
        acc.x = fmaf(u2.x, w2, acc.x); acc.y = fmaf(u2.y, w2, acc.y);
        acc.x = fmaf(u3.x, w3, acc.x); acc.y = fmaf(u3.y, w3, acc.y);
    }
    for (; j < j1; ++j) {
        int s0 = g_csr[j];
        float w0 = g_dinv[s0];
        float2 u0 = h2v[(long long)s0 * 32 + lane];
        acc.x = fmaf(u0.x, w0, acc.x); acc.y = fmaf(u0.y, w0, acc.y);
    }
    float2 bb = reinterpret_cast<const float2*>(b2)[lane];
    float2 o;
    o.x = fmaf(acc.x, dd, bb.x);
    o.y = fmaf(acc.y, dd, bb.y);
    reinterpret_cast<float2*>(out)[(long long)w * 32 + lane] = o;
}

// ---------------- side stream + events (host-side, created once at load) -----
struct GcnStreams {
    cudaStream_t s1 = nullptr;
    cudaEvent_t  e0 = nullptr, e1 = nullptr;
    bool ok = false;
    GcnStreams() {
        if (cudaStreamCreateWithFlags(&s1, cudaStreamNonBlocking) != cudaSuccess) return;
        if (cudaEventCreateWithFlags(&e0, cudaEventDisableTiming) != cudaSuccess) return;
        if (cudaEventCreateWithFlags(&e1, cudaEventDisableTiming) != cudaSuccess) return;
        ok = true;
    }
};
static GcnStreams g_str;

// ---------------- launch ------------------------------------------------------
extern "C" void kernel_launch(void* const* d_in, const int* in_sizes, int n_in,
                              void* d_out, int out_size) {
    const float* x   = (const float*)d_in[0];
    const void*  ei  = d_in[1];
    const float* W1  = (const float*)d_in[2];
    const float* b1  = (const float*)d_in[3];
    const float* W2  = (const float*)d_in[4];
    const float* b2  = (const float*)d_in[5];
    float*       out = (float*)d_out;

    const int N = in_sizes[0] / 128;
    const int E = in_sizes[1] / 2;

    const int TB = 256;
    const int nb = (N + SCAN_B - 1) / SCAN_B;

    const bool fork = g_str.ok;
    cudaStream_t sc = fork ? g_str.s1 : (cudaStream_t)0;   // CSR-chain stream

    if (fork) {
        cudaEventRecord(g_str.e0, 0);
        cudaStreamWaitEvent(sc, g_str.e0, 0);
    }

    // CSR build chain (side stream)
    detect_zero_kernel<<<(N + TB - 1) / TB, TB, 0, sc>>>((const int*)ei, (long long)E, N);
    deg_kernel<<<(E + TB - 1) / TB, TB, 0, sc>>>(ei, E, N);
    scan1_kernel<<<nb, SCAN_B, 0, sc>>>(N);
    scan2_kernel<<<1, 32, 0, sc>>>(nb);
    scan3_kernel<<<(N + TB - 1) / TB, TB, 0, sc>>>(N, E);
    build_kernel<<<(E + TB - 1) / TB, TB, 0, sc>>>(ei, E, N);

    // GEMM1 concurrently on main stream
    gemm1_kernel<<<(N + 31) / 32, 256>>>(x, W1, N);

    if (fork) {
        cudaEventRecord(g_str.e1, sc);
        cudaStreamWaitEvent((cudaStream_t)0, g_str.e1, 0);
    }

    // layer 1 aggregation (needs gemm1 + CSR)
    gather1_kernel<<<(N * 32 + TB - 1) / TB, TB>>>(b1, N);

    // layer 2
    gemm2_kernel<<<(N + 31) / 32, 128>>>(W2, N);
    gather2_kernel<<<(N * 32 + TB - 1) / TB, TB>>>(b2, out, N);
}

// round 8
// speedup vs baseline: 1.2949x; 1.0489x over previous
#include <cuda_runtime.h>
#include <cuda_bf16.h>
#include <cstdint>

// ---------------------------------------------------------------------------
// SlotGCN: 2-layer GCN. R8: portable mma.sync bf16-split GEMMs (3-pass,
// fp32 acc). GEMM outputs bound to __device__ globals INSIDE device code
// (R7 bug: passing g_h1 from host gave the ATS-valid host shadow address).
// N=50000, E=600000, C1=128, C2=64, fp32. Edge dtype auto-detected.
// ---------------------------------------------------------------------------

#define MAXN 50000
#define MAXE 600000
#define SCAN_B 512
#define NBLK ((MAXN + SCAN_B - 1) / SCAN_B)   // 98

__device__ float g_h1[MAXN * 128];
__device__ float g_a1[MAXN * 128];
__device__ float g_h2[MAXN * 64];
__device__ float g_dinv[MAXN];
__device__ int   g_cnt[MAXN];
__device__ int   g_rowptr[MAXN + 1];
__device__ int   g_pos[MAXN];
__device__ int   g_csr[MAXE];
__device__ int   g_bsum[NBLK];
__device__ int   g_boff[NBLK];
__device__ int   g_is64;

__device__ __forceinline__ int load_idx(const void* ei, long long pos, int is64) {
    if (is64) return (int)((const long long*)ei)[pos];
    return ((const int*)ei)[pos];
}

// ======================= mma.sync bf16 (portable sm_80+) =====================
__device__ __forceinline__ void mma_bf16(float* d,
                                         uint32_t a0, uint32_t a1,
                                         uint32_t a2, uint32_t a3,
                                         uint32_t b0, uint32_t b1) {
    asm volatile(
        "mma.sync.aligned.m16n8k16.row.col.f32.bf16.bf16.f32 "
        "{%0,%1,%2,%3}, {%4,%5,%6,%7}, {%8,%9}, {%0,%1,%2,%3};"
        : "+f"(d[0]), "+f"(d[1]), "+f"(d[2]), "+f"(d[3])
        : "r"(a0), "r"(a1), "r"(a2), "r"(a3), "r"(b0), "r"(b1));
}

// H[N,CN] = X[N,128] @ W[128,CN], fp32 via 3-pass bf16 split.
// CTA: 256 threads (8 warps), 128 rows x CN cols. K=128 resident in SMEM.
// SMEM (bf16, k-contiguous, row stride KP=136 -> conflict-free LDS):
//   a_hi[128][KP], a_lo[128][KP], b_hi[CN][KP] (W transposed), b_lo[CN][KP]
template <int CN>
__device__ __forceinline__ void gemm_mma_body(const float* __restrict__ X,
                                              const float* __restrict__ W,
                                              float* __restrict__ H, int N) {
    constexpr int KP = 136;
    constexpr int NT = CN / 8;               // n-tiles per warp
    extern __shared__ __nv_bfloat16 smbf[];
    __nv_bfloat16* a_hi = smbf;
    __nv_bfloat16* a_lo = a_hi + 128 * KP;
    __nv_bfloat16* b_hi = a_lo + 128 * KP;
    __nv_bfloat16* b_lo = b_hi + CN * KP;

    const int tid  = threadIdx.x;
    const int lane = tid & 31;
    const int wrp  = tid >> 5;
    const long long row0 = (long long)blockIdx.x * 128;

    // ---- load X tile -> a_hi/a_lo, zero-pad OOB rows ----
    for (int i = tid; i < 128 * 32; i += 256) {
        int r = i >> 5, c = (i & 31) << 2;
        float4 v = make_float4(0.f, 0.f, 0.f, 0.f);
        if (row0 + r < N)
            v = *reinterpret_cast<const float4*>(X + (row0 + r) * 128 + c);
        float vv[4] = {v.x, v.y, v.z, v.w};
        __nv_bfloat16* ph = &a_hi[r * KP + c];
        __nv_bfloat16* pl = &a_lo[r * KP + c];
#pragma unroll
        for (int j = 0; j < 4; j++) {
            __nv_bfloat16 h = __float2bfloat16(vv[j]);
            ph[j] = h;
            pl[j] = __float2bfloat16(vv[j] - __bfloat162float(h));
        }
    }

    // ---- load W transposed -> b_hi/b_lo: b[n][k] = W[k][n] ----
    for (int i = tid; i < 128 * (CN / 4); i += 256) {
        int kk = i / (CN / 4), nn = (i % (CN / 4)) * 4;
        float4 v = *reinterpret_cast<const float4*>(W + kk * CN + nn);
        float vv[4] = {v.x, v.y, v.z, v.w};
#pragma unroll
        for (int j = 0; j < 4; j++) {
            __nv_bfloat16 h = __float2bfloat16(vv[j]);
            b_hi[(nn + j) * KP + kk] = h;
            b_lo[(nn + j) * KP + kk] =
                __float2bfloat16(vv[j] - __bfloat162float(h));
        }
    }
    __syncthreads();

    // ---- 3-pass MMA: hi*hi + hi*lo + lo*hi, fp32 accumulators ----
    float acc[NT][4];
#pragma unroll
    for (int t = 0; t < NT; t++) {
        acc[t][0] = 0.f; acc[t][1] = 0.f; acc[t][2] = 0.f; acc[t][3] = 0.f;
    }
    const int arow = wrp * 16 + (lane >> 2);     // fragment base row
    const int kc   = (lane & 3) * 2;             // fragment k offset
    const int bn   = lane >> 2;                  // fragment n offset

#pragma unroll
    for (int pass = 0; pass < 3; pass++) {
        const __nv_bfloat16* A = (pass == 2) ? a_lo : a_hi;
        const __nv_bfloat16* B = (pass == 1) ? b_lo : b_hi;
#pragma unroll
        for (int k0 = 0; k0 < 128; k0 += 16) {
            uint32_t A0 = *(const uint32_t*)&A[arow * KP + k0 + kc];
            uint32_t A1 = *(const uint32_t*)&A[(arow + 8) * KP + k0 + kc];
            uint32_t A2 = *(const uint32_t*)&A[arow * KP + k0 + 8 + kc];
            uint32_t A3 = *(const uint32_t*)&A[(arow + 8) * KP + k0 + 8 + kc];
#pragma unroll
            for (int t = 0; t < NT; t++) {
                int n = t * 8 + bn;
                uint32_t B0 = *(const uint32_t*)&B[n * KP + k0 + kc];
                uint32_t B1 = *(const uint32_t*)&B[n * KP + k0 + 8 + kc];
                mma_bf16(acc[t], A0, A1, A2, A3, B0, B1);
            }
        }
    }

    // ---- epilogue: direct float2 stores (fragment layout) ----
    const int r0 = wrp * 16 + (lane >> 2);
    const int c0 = (lane & 3) * 2;
#pragma unroll
    for (int t = 0; t < NT; t++) {
        int col = t * 8 + c0;
        long long gr0 = row0 + r0;
        long long gr1 = gr0 + 8;
        if (gr0 < N)
            *reinterpret_cast<float2*>(&H[gr0 * CN + col]) =
                make_float2(acc[t][0], acc[t][1]);
        if (gr1 < N)
            *reinterpret_cast<float2*>(&H[gr1 * CN + col]) =
                make_float2(acc[t][2], acc[t][3]);
    }
}

// Wrappers: bind device globals in DEVICE code (never pass them from host).
__global__ void __launch_bounds__(256, 1)
gemm1_mma(const float* __restrict__ X, const float* __restrict__ W, int N) {
    gemm_mma_body<128>(X, W, g_h1, N);
}
__global__ void __launch_bounds__(256, 1)
gemm2_mma(const float* __restrict__ W, int N) {
    gemm_mma_body<64>(g_a1, W, g_h2, N);
}

// ======================= CSR build chain =====================================
__global__ void detect_zero_kernel(const int* __restrict__ ei32,
                                   long long half_words, int N) {
    int i = blockIdx.x * blockDim.x + threadIdx.x;
    if (i < N) g_cnt[i] = 0;
    if (blockIdx.x == 0) {
        __shared__ int nz;
        if (threadIdx.x == 0) nz = 0;
        __syncthreads();
        for (int k = threadIdx.x; k < 4096; k += blockDim.x) {
            long long w = ((long long)k * 1315423911u) % half_words;
            if (ei32[2 * w + 1] != 0) atomicAdd(&nz, 1);
        }
        __syncthreads();
        if (threadIdx.x == 0) g_is64 = (nz == 0) ? 1 : 0;
    }
}

__global__ void deg_kernel(const void* __restrict__ ei, int E, int N) {
    int e = blockIdx.x * blockDim.x + threadIdx.x;
    if (e >= E) return;
    int is64 = g_is64;
    int d = load_idx(ei, (long long)E + e, is64);
    if ((unsigned)d < (unsigned)N) atomicAdd(&g_cnt[d], 1);
}

__global__ void scan1_kernel(int N) {
    __shared__ int sh[SCAN_B];
    int t = threadIdx.x;
    int i = blockIdx.x * SCAN_B + t;
    int v = (i < N) ? g_cnt[i] : 0;
    if (i < N) g_dinv[i] = rsqrtf((float)v + 1.0f);
    sh[t] = v;
    __syncthreads();
#pragma unroll
    for (int o = 1; o < SCAN_B; o <<= 1) {
        int x = (t >= o) ? sh[t - o] : 0;
        __syncthreads();
        sh[t] += x;
        __syncthreads();
    }
    if (i < N) g_rowptr[i] = sh[t] - v;
    if (t == SCAN_B - 1) g_bsum[blockIdx.x] = sh[t];
}

__global__ void scan2_kernel(int nb) {
    __shared__ int sh[128];
    int t = threadIdx.x;
    int v = (t < nb) ? g_bsum[t] : 0;
    sh[t] = v;
    __syncthreads();
#pragma unroll
    for (int o = 1; o < 128; o <<= 1) {
        int x = (t >= o) ? sh[t - o] : 0;
        __syncthreads();
        sh[t] += x;
        __syncthreads();
    }
    if (t < nb) g_boff[t] = sh[t] - v;
}

__global__ void scan3_kernel(int N, int E) {
    int i = blockIdx.x * blockDim.x + threadIdx.x;
    if (i < N) {
        int r = g_rowptr[i] + g_boff[i / SCAN_B];
        g_rowptr[i] = r;
        g_pos[i] = r;
    }
    if (i == 0) g_rowptr[N] = E;
}

__global__ void build_kernel(const void* __restrict__ ei, int E, int N) {
    int e = blockIdx.x * blockDim.x + threadIdx.x;
    if (e >= E) return;
    int is64 = g_is64;
    int d = load_idx(ei, (long long)E + e, is64);
    int s = load_idx(ei, (long long)e, is64);
    if ((unsigned)d < (unsigned)N && (unsigned)s < (unsigned)N) {
        int p = atomicAdd(&g_pos[d], 1);
        if (p < MAXE) g_csr[p] = s;
    }
}

// ======================= fallback SIMT GEMM (shape guard) ====================
template <int C>
__device__ __forceinline__ void gemm_body(const float* __restrict__ X,
                                          const float* __restrict__ W,
                                          float* __restrict__ H, int N) {
    constexpr int CT = C / 4;
    __shared__ float xs[32][33];
    __shared__ float ws[32][C];
    const int tid = threadIdx.x;
    const int ct = tid % CT;
    const int rt = tid / CT;
    const int row0 = blockIdx.x * 32;
    const int nthr = CT * 8;
    float acc[4][4];
#pragma unroll
    for (int r = 0; r < 4; r++)
#pragma unroll
        for (int c = 0; c < 4; c++) acc[r][c] = 0.f;
    for (int k0 = 0; k0 < 128; k0 += 32) {
        for (int i = tid; i < 32 * 32; i += nthr) {
            int r = i >> 5, k = i & 31;
            int grow = row0 + r;
            xs[r][k] = (grow < N) ? X[(long long)grow * 128 + k0 + k] : 0.f;
        }
        for (int i = tid; i < 32 * C; i += nthr) {
            int k = i / C, c = i % C;
            ws[k][c] = W[(k0 + k) * C + c];
        }
        __syncthreads();
#pragma unroll
        for (int k = 0; k < 32; k++) {
            float4 b = *reinterpret_cast<const float4*>(&ws[k][ct * 4]);
#pragma unroll
            for (int r = 0; r < 4; r++) {
                float a = xs[rt * 4 + r][k];
                acc[r][0] = fmaf(a, b.x, acc[r][0]);
                acc[r][1] = fmaf(a, b.y, acc[r][1]);
                acc[r][2] = fmaf(a, b.z, acc[r][2]);
                acc[r][3] = fmaf(a, b.w, acc[r][3]);
            }
        }
        __syncthreads();
    }
#pragma unroll
    for (int r = 0; r < 4; r++) {
        int grow = row0 + rt * 4 + r;
        if (grow < N) {
            float4 v = make_float4(acc[r][0], acc[r][1], acc[r][2], acc[r][3]);
            *reinterpret_cast<float4*>(&H[(long long)grow * C + ct * 4]) = v;
        }
    }
}
__global__ void gemm1_simt(const float* __restrict__ X,
                           const float* __restrict__ W, int N) {
    gemm_body<128>(X, W, g_h1, N);
}
__global__ void gemm2_simt(const float* __restrict__ W, int N) {
    gemm_body<64>(g_a1, W, g_h2, N);
}

// ======================= gathers (fused epilogue) ============================
__global__ void gather1_kernel(const float* __restrict__ b1, int N) {
    int w = (blockIdx.x * blockDim.x + threadIdx.x) >> 5;
    int lane = threadIdx.x & 31;
    if (w >= N) return;
    float dd = g_dinv[w];
    const float4* h1v = reinterpret_cast<const float4*>(g_h1);
    float4 v = h1v[(long long)w * 32 + lane];
    float4 acc = make_float4(v.x * dd, v.y * dd, v.z * dd, v.w * dd);
    int j = g_rowptr[w];
    int j1 = g_rowptr[w + 1];
    for (; j + 3 < j1; j += 4) {
        int s0 = g_csr[j], s1 = g_csr[j + 1], s2 = g_csr[j + 2], s3 = g_csr[j + 3];
        float w0 = g_dinv[s0], w1 = g_dinv[s1], w2 = g_dinv[s2], w3 = g_dinv[s3];
        float4 u0 = h1v[(long long)s0 * 32 + lane];
        float4 u1 = h1v[(long long)s1 * 32 + lane];
        float4 u2 = h1v[(long long)s2 * 32 + lane];
        float4 u3 = h1v[(long long)s3 * 32 + lane];
        acc.x = fmaf(u0.x, w0, acc.x); acc.y = fmaf(u0.y, w0, acc.y);
        acc.z = fmaf(u0.z, w0, acc.z); acc.w = fmaf(u0.w, w0, acc.w);
        acc.x = fmaf(u1.x, w1, acc.x); acc.y = fmaf(u1.y, w1, acc.y);
        acc.z = fmaf(u1.z, w1, acc.z); acc.w = fmaf(u1.w, w1, acc.w);
        acc.x = fmaf(u2.x, w2, acc.x); acc.y = fmaf(u2.y, w2, acc.y);
        acc.z = fmaf(u2.z, w2, acc.z); acc.w = fmaf(u2.w, w2, acc.w);
        acc.x = fmaf(u3.x, w3, acc.x); acc.y = fmaf(u3.y, w3, acc.y);
        acc.z = fmaf(u3.z, w3, acc.z); acc.w = fmaf(u3.w, w3, acc.w);
    }
    for (; j < j1; ++j) {
        int s0 = g_csr[j];
        float w0 = g_dinv[s0];
        float4 u0 = h1v[(long long)s0 * 32 + lane];
        acc.x = fmaf(u0.x, w0, acc.x); acc.y = fmaf(u0.y, w0, acc.y);
        acc.z = fmaf(u0.z, w0, acc.z); acc.w = fmaf(u0.w, w0, acc.w);
    }
    float4 bb = reinterpret_cast<const float4*>(b1)[lane];
    float4 o;
    o.x = fmaxf(fmaf(acc.x, dd, bb.x), 0.f);
    o.y = fmaxf(fmaf(acc.y, dd, bb.y), 0.f);
    o.z = fmaxf(fmaf(acc.z, dd, bb.z), 0.f);
    o.w = fmaxf(fmaf(acc.w, dd, bb.w), 0.f);
    reinterpret_cast<float4*>(g_a1)[(long long)w * 32 + lane] = o;
}

__global__ void gather2_kernel(const float* __restrict__ b2,
                               float* __restrict__ out, int N) {
    int w = (blockIdx.x * blockDim.x + threadIdx.x) >> 5;
    int lane = threadIdx.x & 31;
    if (w >= N) return;
    float dd = g_dinv[w];
    const float2* h2v = reinterpret_cast<const float2*>(g_h2);
    float2 v = h2v[(long long)w * 32 + lane];
    float2 acc = make_float2(v.x * dd, v.y * dd);
    int j = g_rowptr[w];
    int j1 = g_rowptr[w + 1];
    for (; j + 3 < j1; j += 4) {
        int s0 = g_csr[j], s1 = g_csr[j + 1], s2 = g_csr[j + 2], s3 = g_csr[j + 3];
        float w0 = g_dinv[s0], w1 = g_dinv[s1], w2 = g_dinv[s2], w3 = g_dinv[s3];
        float2 u0 = h2v[(long long)s0 * 32 + lane];
        float2 u1 = h2v[(long long)s1 * 32 + lane];
        float2 u2 = h2v[(long long)s2 * 32 + lane];
        float2 u3 = h2v[(long long)s3 * 32 + lane];
        acc.x = fmaf(u0.x, w0, acc.x); acc.y = fmaf(u0.y, w0, acc.y);
        acc.x = fmaf(u1.x, w1, acc.x); acc.y = fmaf(u1.y, w1, acc.y);
        acc.x = fmaf(u2.x, w2, acc.x); acc.y = fmaf(u2.y, w2, acc.y);
        acc.x = fmaf(u3.x, w3, acc.x); acc.y = fmaf(u3.y, w3, acc.y);
    }
    for (; j < j1; ++j) {
        int s0 = g_csr[j];
        float w0 = g_dinv[s0];
        float2 u0 = h2v[(long long)s0 * 32 + lane];
        acc.x = fmaf(u0.x, w0, acc.x); acc.y = fmaf(u0.y, w0, acc.y);
    }
    float2 bb = reinterpret_cast<const float2*>(b2)[lane];
    float2 o;
    o.x = fmaf(acc.x, dd, bb.x);
    o.y = fmaf(acc.y, dd, bb.y);
    reinterpret_cast<float2*>(out)[(long long)w * 32 + lane] = o;
}

// ======================= host-side stream/event (once) ======================
struct GcnStreams {
    cudaStream_t s1 = nullptr;
    cudaEvent_t e0 = nullptr, e1 = nullptr;
    bool ok = false;
    GcnStreams() {
        if (cudaStreamCreateWithFlags(&s1, cudaStreamNonBlocking) != cudaSuccess) return;
        if (cudaEventCreateWithFlags(&e0, cudaEventDisableTiming) != cudaSuccess) return;
        if (cudaEventCreateWithFlags(&e1, cudaEventDisableTiming) != cudaSuccess) return;
        ok = true;
    }
};
static GcnStreams g_str;

// ======================= launch ==============================================
extern "C" void kernel_launch(void* const* d_in, const int* in_sizes, int n_in,
                              void* d_out, int out_size) {
    const float* x   = (const float*)d_in[0];
    const void*  ei  = d_in[1];
    const float* W1  = (const float*)d_in[2];
    const float* b1  = (const float*)d_in[3];
    const float* W2  = (const float*)d_in[4];
    const float* b2  = (const float*)d_in[5];
    float*       out = (float*)d_out;

    const int N = in_sizes[0] / 128;
    const int E = in_sizes[1] / 2;
    const bool tc_ok = (in_sizes[2] == 128 * 128) && (in_sizes[4] == 128 * 64);

    const int TB = 256;
    const int nb = (N + SCAN_B - 1) / SCAN_B;

    // dynamic smem: (a_hi + a_lo + b_hi + b_lo) bf16, KP=136
    const int smem1 = (2 * 128 * 136 + 2 * 128 * 136) * 2;  // 139264 B
    const int smem2 = (2 * 128 * 136 + 2 * 64 * 136) * 2;   // 104448 B
    cudaFuncSetAttribute(gemm1_mma,
                         cudaFuncAttributeMaxDynamicSharedMemorySize, smem1);
    cudaFuncSetAttribute(gemm2_mma,
                         cudaFuncAttributeMaxDynamicSharedMemorySize, smem2);

    const bool fork = g_str.ok;
    cudaStream_t sc = fork ? g_str.s1 : (cudaStream_t)0;

    if (fork) {
        cudaEventRecord(g_str.e0, 0);
        cudaStreamWaitEvent(sc, g_str.e0, 0);
    }

    // CSR build chain (side stream)
    detect_zero_kernel<<<(N + TB - 1) / TB, TB, 0, sc>>>((const int*)ei, (long long)E, N);
    deg_kernel<<<(E + TB - 1) / TB, TB, 0, sc>>>(ei, E, N);
    scan1_kernel<<<nb, SCAN_B, 0, sc>>>(N);
    scan2_kernel<<<1, 128, 0, sc>>>(nb);
    scan3_kernel<<<(N + TB - 1) / TB, TB, 0, sc>>>(N, E);
    build_kernel<<<(E + TB - 1) / TB, TB, 0, sc>>>(ei, E, N);

    // GEMM1 concurrently on main stream
    if (tc_ok) {
        gemm1_mma<<<(N + 127) / 128, 256, smem1>>>(x, W1, N);
    } else {
        gemm1_simt<<<(N + 31) / 32, 256>>>(x, W1, N);
    }

    if (fork) {
        cudaEventRecord(g_str.e1, sc);
        cudaStreamWaitEvent((cudaStream_t)0, g_str.e1, 0);
    }

    gather1_kernel<<<(N * 32 + TB - 1) / TB, TB>>>(b1, N);

    if (tc_ok) {
        gemm2_mma<<<(N + 127) / 128, 256, smem2>>>(W2, N);
    } else {
        gemm2_simt<<<(N + 31) / 32, 128>>>(W2, N);
    }
    gather2_kernel<<<(N * 32 + TB - 1) / TB, TB>>>(b2, out, N);
}